// round 15
// baseline (speedup 1.0000x reference)
#include <cuda_runtime.h>
#include <cuda_bf16.h>
#include <math.h>
#include <stdint.h>

// Problem constants
#define BATCH 2
#define SEQ   2048
#define HID   1024
#define NHEAD 16
#define HD    64
#define QKVN  3072
#define MTOT  (BATCH * SEQ)   // 4096
#define GEMM_K 1024

// ---------------------------------------------------------------------------
// Scratch (device globals; no allocation allowed)
// ---------------------------------------------------------------------------
__device__ float g_qkv [MTOT * QKVN];

__device__ __nv_bfloat16 g_Xhi[MTOT * HID];
__device__ __nv_bfloat16 g_Xlo[MTOT * HID];
__device__ __nv_bfloat16 g_W1hi[QKVN * HID];
__device__ __nv_bfloat16 g_W1lo[QKVN * HID];
__device__ __nv_bfloat16 g_W2hi[HID * HID];
__device__ __nv_bfloat16 g_W2lo[HID * HID];
__device__ __nv_bfloat16 g_Ahi[MTOT * HID];
__device__ __nv_bfloat16 g_Alo[MTOT * HID];

#define BHSZ (BATCH * NHEAD * SEQ * HD)
__device__ __nv_bfloat16 g_Qhi[BHSZ];
__device__ __nv_bfloat16 g_Qlo[BHSZ];
__device__ __nv_bfloat16 g_Khi[BHSZ];
__device__ __nv_bfloat16 g_Klo[BHSZ];
__device__ __nv_bfloat16 g_Vhi[BHSZ];
__device__ __nv_bfloat16 g_Vlo[BHSZ];

// ---------------------------------------------------------------------------
// PTX helpers (compute_103-safe)
// ---------------------------------------------------------------------------
__device__ __forceinline__ uint32_t smem_u32(const void* p) {
    uint32_t a;
    asm("{ .reg .u64 t; cvta.to.shared.u64 t, %1; cvt.u32.u64 %0, t; }"
        : "=r"(a) : "l"(p));
    return a;
}

#define CP16(dst, src) \
    asm volatile("cp.async.ca.shared.global [%0], [%1], 16;" :: "r"(dst), "l"(src))
#define CP_COMMIT() asm volatile("cp.async.commit_group;" ::: "memory")
#define CP_WAIT(n)  asm volatile("cp.async.wait_group %0;" :: "n"(n) : "memory")

#define LDM4(r, a) \
    asm volatile("ldmatrix.sync.aligned.m8n8.x4.shared.b16 {%0,%1,%2,%3}, [%4];" \
        : "=r"((r)[0]), "=r"((r)[1]), "=r"((r)[2]), "=r"((r)[3]) : "r"(a))
#define LDM4T(r, a) \
    asm volatile("ldmatrix.sync.aligned.m8n8.x4.trans.shared.b16 {%0,%1,%2,%3}, [%4];" \
        : "=r"((r)[0]), "=r"((r)[1]), "=r"((r)[2]), "=r"((r)[3]) : "r"(a))
#define LDM2(r, a) \
    asm volatile("ldmatrix.sync.aligned.m8n8.x2.shared.b16 {%0,%1}, [%2];" \
        : "=r"((r)[0]), "=r"((r)[1]) : "r"(a))
#define MMA_BF16(c, a, b) \
    asm volatile("mma.sync.aligned.m16n8k16.row.col.f32.bf16.bf16.f32 " \
        "{%0,%1,%2,%3}, {%4,%5,%6,%7}, {%8,%9}, {%0,%1,%2,%3};" \
        : "+f"((c)[0]), "+f"((c)[1]), "+f"((c)[2]), "+f"((c)[3]) \
        : "r"((a)[0]), "r"((a)[1]), "r"((a)[2]), "r"((a)[3]), \
          "r"((b)[0]), "r"((b)[1]))
// variant with explicit A regs (for P packed inside the S float array)
#define MMA_BF16_A(c, a0, a1, a2, a3, b) \
    asm volatile("mma.sync.aligned.m16n8k16.row.col.f32.bf16.bf16.f32 " \
        "{%0,%1,%2,%3}, {%4,%5,%6,%7}, {%8,%9}, {%0,%1,%2,%3};" \
        : "+f"((c)[0]), "+f"((c)[1]), "+f"((c)[2]), "+f"((c)[3]) \
        : "r"(a0), "r"(a1), "r"(a2), "r"(a3), \
          "r"((b)[0]), "r"((b)[1]))

__device__ __forceinline__ float ex2f(float x) {
    float y;
    asm("ex2.approx.f32 %0, %1;" : "=f"(y) : "f"(x));
    return y;
}
// pack two floats to bf16x2: lo half = a, hi half = b
__device__ __forceinline__ uint32_t packbf(float a, float b) {
    uint32_t d;
    asm("cvt.rn.bf16x2.f32 %0, %1, %2;" : "=r"(d) : "f"(b), "f"(a));
    return d;
}
__device__ __forceinline__ float lo16f(uint32_t h) { return __uint_as_float(h << 16); }
__device__ __forceinline__ float hi16f(uint32_t h) { return __uint_as_float(h & 0xffff0000u); }

__device__ __forceinline__ void wsplit(__nv_bfloat16* hi, __nv_bfloat16* lo,
                                       size_t i, float v) {
    __nv_bfloat16 h = __float2bfloat16(v);
    hi[i] = h;
    lo[i] = __float2bfloat16(v - __bfloat162float(h));
}

// ---------------------------------------------------------------------------
// Prep kernels
// ---------------------------------------------------------------------------
__global__ void split_f32(const float* __restrict__ in, __nv_bfloat16* __restrict__ hi,
                          __nv_bfloat16* __restrict__ lo, int n) {
    int i = blockIdx.x * 256 + threadIdx.x;
    if (i >= n) return;
    float v = in[i];
    __nv_bfloat16 h = __float2bfloat16(v);
    hi[i] = h;
    lo[i] = __float2bfloat16(v - __bfloat162float(h));
}

__global__ void transpose_split(const float* __restrict__ in, __nv_bfloat16* __restrict__ hi,
                                __nv_bfloat16* __restrict__ lo, int K, int N) {
    __shared__ float t[32][33];
    int n0 = blockIdx.x * 32, k0 = blockIdx.y * 32;
    int tx = threadIdx.x, ty = threadIdx.y;
    #pragma unroll
    for (int i = 0; i < 32; i += 8)
        t[ty + i][tx] = in[(size_t)(k0 + ty + i) * N + n0 + tx];
    __syncthreads();
    #pragma unroll
    for (int i = 0; i < 32; i += 8) {
        float v = t[tx][ty + i];
        size_t o = (size_t)(n0 + ty + i) * K + k0 + tx;
        __nv_bfloat16 h = __float2bfloat16(v);
        hi[o] = h;
        lo[o] = __float2bfloat16(v - __bfloat162float(h));
    }
}

// ---------------------------------------------------------------------------
// Warp-MMA bf16x3 GEMM (validated; unchanged)
// ---------------------------------------------------------------------------
#define RS 40
#define TILE_SB  (128 * RS * 2)
#define BUF_SB   (4 * TILE_SB)
#define GEMM_DSMEM (2 * BUF_SB)

__device__ __forceinline__ void cp_tile(uint32_t dst, const __nv_bfloat16* __restrict__ src,
                                        int row0, int k0, int tid) {
    #pragma unroll
    for (int i = 0; i < 2; i++) {
        int idx = tid + i * 256;
        int r = idx >> 2, seg = idx & 3;
        CP16(dst + (uint32_t)(r * RS + seg * 8) * 2,
             src + (size_t)(row0 + r) * GEMM_K + k0 + seg * 8);
    }
}

__global__ __launch_bounds__(256) void gemm_mma_bf16x3(
    const __nv_bfloat16* __restrict__ Ahi, const __nv_bfloat16* __restrict__ Alo,
    const __nv_bfloat16* __restrict__ Bhi, const __nv_bfloat16* __restrict__ Blo,
    const float* __restrict__ bias, float* __restrict__ C, int N)
{
    extern __shared__ char dsm[];
    const uint32_t sbase = smem_u32(dsm);
    const int tid  = threadIdx.x;
    const int lane = tid & 31;
    const int wid  = tid >> 5;
    const int wm   = wid >> 2;
    const int wn   = wid & 3;
    const int m0 = blockIdx.y * 128;
    const int n0 = blockIdx.x * 128;

    float acc[4][4][4] = {};

    {
        uint32_t bb = sbase;
        cp_tile(bb,               Ahi, m0, 0, tid);
        cp_tile(bb + TILE_SB,     Alo, m0, 0, tid);
        cp_tile(bb + 2 * TILE_SB, Bhi, n0, 0, tid);
        cp_tile(bb + 3 * TILE_SB, Blo, n0, 0, tid);
        CP_COMMIT();
    }

    const int a_lr = lane & 15, a_lc = lane >> 4;
    const int b_lr = lane & 7,  b_lc = (lane >> 3) & 1;

    #pragma unroll 1
    for (int c = 0; c < GEMM_K / 32; c++) {
        if (c + 1 < GEMM_K / 32) {
            int k0 = (c + 1) * 32;
            uint32_t bb = sbase + ((c + 1) & 1) * BUF_SB;
            cp_tile(bb,               Ahi, m0, k0, tid);
            cp_tile(bb + TILE_SB,     Alo, m0, k0, tid);
            cp_tile(bb + 2 * TILE_SB, Bhi, n0, k0, tid);
            cp_tile(bb + 3 * TILE_SB, Blo, n0, k0, tid);
            CP_COMMIT();
            CP_WAIT(1);
        } else {
            CP_WAIT(0);
        }
        __syncthreads();

        uint32_t bb = sbase + (c & 1) * BUF_SB;
        #pragma unroll
        for (int ks = 0; ks < 2; ks++) {
            uint32_t Ah[4][4], Al[4][4], Bh[4][2], Bl[4][2];
            #pragma unroll
            for (int mf = 0; mf < 4; mf++) {
                uint32_t off = (uint32_t)((wm * 64 + mf * 16 + a_lr) * RS
                                          + ks * 16 + a_lc * 8) * 2;
                LDM4(Ah[mf], bb + off);
                LDM4(Al[mf], bb + TILE_SB + off);
            }
            #pragma unroll
            for (int nf = 0; nf < 4; nf++) {
                uint32_t off = (uint32_t)((wn * 32 + nf * 8 + b_lr) * RS
                                          + ks * 16 + b_lc * 8) * 2;
                LDM2(Bh[nf], bb + 2 * TILE_SB + off);
                LDM2(Bl[nf], bb + 3 * TILE_SB + off);
            }
            #pragma unroll
            for (int mf = 0; mf < 4; mf++)
                #pragma unroll
                for (int nf = 0; nf < 4; nf++)
                    MMA_BF16(acc[mf][nf], Ah[mf], Bh[nf]);
            #pragma unroll
            for (int mf = 0; mf < 4; mf++)
                #pragma unroll
                for (int nf = 0; nf < 4; nf++)
                    MMA_BF16(acc[mf][nf], Ah[mf], Bl[nf]);
            #pragma unroll
            for (int mf = 0; mf < 4; mf++)
                #pragma unroll
                for (int nf = 0; nf < 4; nf++)
                    MMA_BF16(acc[mf][nf], Al[mf], Bh[nf]);
        }
        __syncthreads();
    }

    const int r0 = m0 + wm * 64 + (lane >> 2);
    const int c0 = n0 + wn * 32 + (lane & 3) * 2;
    #pragma unroll
    for (int mf = 0; mf < 4; mf++) {
        #pragma unroll
        for (int nf = 0; nf < 4; nf++) {
            int col = c0 + nf * 8;
            float bx = bias[col], by = bias[col + 1];
            int ra = r0 + mf * 16;
            float2 v0 = {acc[mf][nf][0] + bx, acc[mf][nf][1] + by};
            float2 v1 = {acc[mf][nf][2] + bx, acc[mf][nf][3] + by};
            *reinterpret_cast<float2*>(&C[(size_t)ra * N + col]) = v0;
            *reinterpret_cast<float2*>(&C[(size_t)(ra + 8) * N + col]) = v1;
        }
    }
}

// ---------------------------------------------------------------------------
// RoPE + scatter (unchanged from R12)
// ---------------------------------------------------------------------------
#define QSCALE 0.1803368801111244f   // 0.125 * log2(e)

__global__ void rope_scatter()
{
    int i = blockIdx.x * blockDim.x + threadIdx.x;     // over (b,h,l,j), j<32
    const int total = BATCH * NHEAD * SEQ * 32;
    if (i >= total) return;

    int j = i & 31;
    int l = (i >> 5) & (SEQ - 1);
    int h = (i >> 16) & (NHEAD - 1);
    int b = i >> 20;

    const float* base = g_qkv + ((size_t)(b * SEQ + l)) * QKVN + h * 192;
    size_t o = ((((size_t)(b * NHEAD + h)) * SEQ + l) << 6) + j;   // [b][h][l][j]

    wsplit(g_Vhi, g_Vlo, o,      base[128 + j]);
    wsplit(g_Vhi, g_Vlo, o + 32, base[160 + j]);

    double e = -((double)(2 * j) / 64.0) * 13.287712379549449;  // log2(10000)
    float inv_freq = (float)exp2(e);
    float fr = (float)l * inv_freq;
    float c = cosf(fr), s = sinf(fr);

    float q1 = base[j],      q2 = base[j + 32];
    float k1 = base[64 + j], k2 = base[96 + j];

    wsplit(g_Qhi, g_Qlo, o,      (q1 * c - q2 * s) * QSCALE);
    wsplit(g_Qhi, g_Qlo, o + 32, (q1 * s + q2 * c) * QSCALE);
    wsplit(g_Khi, g_Klo, o,      k1 * c - k2 * s);
    wsplit(g_Khi, g_Klo, o + 32, k1 * s + k2 * c);
}

// ---------------------------------------------------------------------------
// Flash attention on HMMA, software-pipelined across tiles:
//   per iter: [wait+bar] -> cp(t+2) -> QK(t+1) -> PV(t) -> softmax(t+1)
// so PV(t)+QK(t+1) HMMAs execute while softmax runs on ALU/MUFU.
// P is packed in place into S's registers; two S sets ping-pong.
// 3-stage KV ring; one barrier per tile; 1 CTA/SM (smem 147KB).
// ---------------------------------------------------------------------------
#define FRS    72                        // smem row stride (bf16 elems) = 144B
#define FTS    (64 * FRS * 2)            // 9216 B per 64-row tile
#define FTS128 (128 * FRS * 2)           // 18432 B per 128-row tile
#define FBUF   (4 * FTS)                 // Khi,Klo,Vhi,Vlo = 36864 B
#define QREG   (2 * FTS128)              // Qhi,Qlo = 36864 B
#define FDSMEM (QREG + 3 * FBUF)         // 147456 B
#define NTILES (SEQ / 64)                // 32

__device__ __forceinline__ void cp_tile64(uint32_t dst, const __nv_bfloat16* __restrict__ src,
                                          int tid) {
    #pragma unroll
    for (int i = 0; i < 2; i++) {
        int idx = tid + i * 256;
        int r = idx >> 3, seg = idx & 7;
        CP16(dst + (uint32_t)(r * (FRS * 2) + seg * 16),
             src + (size_t)r * HD + seg * 8);
    }
}

__device__ __forceinline__ void cp_tile128(uint32_t dst, const __nv_bfloat16* __restrict__ src,
                                           int tid) {
    #pragma unroll
    for (int i = 0; i < 4; i++) {
        int idx = tid + i * 256;
        int r = idx >> 3, seg = idx & 7;
        CP16(dst + (uint32_t)(r * (FRS * 2) + seg * 16),
             src + (size_t)r * HD + seg * 8);
    }
}

__global__ __launch_bounds__(256) void flash_mma()
{
    extern __shared__ char dsm[];
    const uint32_t sbase = smem_u32(dsm);
    const int tid  = threadIdx.x;
    const int lane = tid & 31;
    const int wid  = tid >> 5;
    const int bh   = blockIdx.y;

    const size_t bhoff = (size_t)bh * SEQ * HD;
    const int qrow0 = blockIdx.x * 128;
    const int r0 = qrow0 + wid * 16 + (lane >> 2);
    const int cc = (lane & 3) * 2;

    // A-frag (Q) smem lane address
    const uint32_t qbase = sbase +
        (uint32_t)((wid * 16 + (lane & 15)) * FRS + (lane >> 4) * 8) * 2;
    // B-frag (K, non-trans) lane address components
    const uint32_t k_row = (lane & 7) + ((lane >> 4) & 1) * 8;
    const uint32_t k_col = ((lane >> 3) & 1) * 8;
    // B-frag (V, trans) lane address components
    const uint32_t v_row = (lane & 7) + ((lane >> 3) & 1) * 8;
    const uint32_t v_col = ((lane >> 4) & 1) * 8;

    float O[8][4] = {};
    float S0[8][4], S1[8][4];
    float m0 = -1e30f, m1 = -1e30f, l0 = 0.f, l1 = 0.f;

    // ---- QK into Sn (zeroes Sn first) ----
    auto qk_tile = [&](int t, float (&Sn)[8][4]) {
        const uint32_t kb = sbase + QREG + (t % 3) * FBUF;
        #pragma unroll
        for (int nf = 0; nf < 8; nf++)
            #pragma unroll
            for (int c = 0; c < 4; c++) Sn[nf][c] = 0.f;
        #pragma unroll
        for (int kc = 0; kc < 4; kc++) {
            uint32_t Qh[4], Ql[4];
            LDM4(Qh, qbase + kc * 32);
            LDM4(Ql, qbase + FTS128 + kc * 32);
            #pragma unroll
            for (int np = 0; np < 4; np++) {
                uint32_t Bh[4], Bl[4];
                uint32_t off = (np * 16 + k_row) * (FRS * 2) + (kc * 16 + k_col) * 2;
                LDM4(Bh, kb + off);
                LDM4(Bl, kb + FTS + off);
                MMA_BF16(Sn[2 * np],     Qh, &Bh[0]);
                MMA_BF16(Sn[2 * np + 1], Qh, &Bh[2]);
                MMA_BF16(Sn[2 * np],     Qh, &Bl[0]);
                MMA_BF16(Sn[2 * np + 1], Qh, &Bl[2]);
                MMA_BF16(Sn[2 * np],     Ql, &Bh[0]);
                MMA_BF16(Sn[2 * np + 1], Ql, &Bh[2]);
            }
        }
    };

    // ---- PV from packed P (in Sc) ----
    auto pv_tile = [&](int t, float (&Sc)[8][4]) {
        const uint32_t vb = sbase + QREG + (t % 3) * FBUF + 2 * FTS;
        #pragma unroll
        for (int kc = 0; kc < 4; kc++) {
            uint32_t ph0 = __float_as_uint(Sc[2 * kc][0]);
            uint32_t ph1 = __float_as_uint(Sc[2 * kc][1]);
            uint32_t ph2 = __float_as_uint(Sc[2 * kc + 1][0]);
            uint32_t ph3 = __float_as_uint(Sc[2 * kc + 1][1]);
            uint32_t pl0 = __float_as_uint(Sc[2 * kc][2]);
            uint32_t pl1 = __float_as_uint(Sc[2 * kc][3]);
            uint32_t pl2 = __float_as_uint(Sc[2 * kc + 1][2]);
            uint32_t pl3 = __float_as_uint(Sc[2 * kc + 1][3]);
            #pragma unroll
            for (int np = 0; np < 4; np++) {
                uint32_t Vh[4], Vl[4];
                uint32_t off = (kc * 16 + v_row) * (FRS * 2) + (np * 16 + v_col) * 2;
                LDM4T(Vh, vb + off);
                LDM4T(Vl, vb + FTS + off);
                MMA_BF16_A(O[2 * np],     ph0, ph1, ph2, ph3, &Vh[0]);
                MMA_BF16_A(O[2 * np + 1], ph0, ph1, ph2, ph3, &Vh[2]);
                MMA_BF16_A(O[2 * np],     ph0, ph1, ph2, ph3, &Vl[0]);
                MMA_BF16_A(O[2 * np + 1], ph0, ph1, ph2, ph3, &Vl[2]);
                MMA_BF16_A(O[2 * np],     pl0, pl1, pl2, pl3, &Vh[0]);
                MMA_BF16_A(O[2 * np + 1], pl0, pl1, pl2, pl3, &Vh[2]);
            }
        }
    };

    // ---- softmax on Sn, packing P in place; rescales O, updates m/l ----
    auto softmax_tile = [&](float (&Sn)[8][4]) {
        float tm0 = -1e30f, tm1 = -1e30f;
        #pragma unroll
        for (int nf = 0; nf < 8; nf++) {
            tm0 = fmaxf(tm0, fmaxf(Sn[nf][0], Sn[nf][1]));
            tm1 = fmaxf(tm1, fmaxf(Sn[nf][2], Sn[nf][3]));
        }
        tm0 = fmaxf(tm0, __shfl_xor_sync(0xffffffff, tm0, 1));
        tm0 = fmaxf(tm0, __shfl_xor_sync(0xffffffff, tm0, 2));
        tm1 = fmaxf(tm1, __shfl_xor_sync(0xffffffff, tm1, 1));
        tm1 = fmaxf(tm1, __shfl_xor_sync(0xffffffff, tm1, 2));

        float mn0 = fmaxf(m0, tm0), mn1 = fmaxf(m1, tm1);
        float corr0 = ex2f(m0 - mn0), corr1 = ex2f(m1 - mn1);
        m0 = mn0; m1 = mn1;

        float rs0 = 0.f, rs1 = 0.f;
        #pragma unroll
        for (int nf = 0; nf < 8; nf++) {
            float p0 = ex2f(Sn[nf][0] - mn0), p1 = ex2f(Sn[nf][1] - mn0);
            float p2 = ex2f(Sn[nf][2] - mn1), p3 = ex2f(Sn[nf][3] - mn1);
            rs0 += p0 + p1;
            rs1 += p2 + p3;
            uint32_t h01 = packbf(p0, p2), h23 = packbf(p1, p3);
            // note: A-frag k-order: {(r,k0),(r,k1)} packed pairs along k.
            // pack (p0,p2) = rows r/r+8? No — see mapping below.
            (void)h01; (void)h23;
            // correct mapping (same as validated R12): pairs along columns
            uint32_t a01 = packbf(p0, p1);             // cols 2c,2c+1 row r
            uint32_t a23 = packbf(p2, p3);             // cols 2c,2c+1 row r+8
            uint32_t b01 = packbf(p0 - lo16f(a01), p1 - hi16f(a01));
            uint32_t b23 = packbf(p2 - lo16f(a23), p3 - hi16f(a23));
            Sn[nf][0] = __uint_as_float(a01);
            Sn[nf][1] = __uint_as_float(a23);
            Sn[nf][2] = __uint_as_float(b01);
            Sn[nf][3] = __uint_as_float(b23);
        }
        rs0 += __shfl_xor_sync(0xffffffff, rs0, 1);
        rs0 += __shfl_xor_sync(0xffffffff, rs0, 2);
        rs1 += __shfl_xor_sync(0xffffffff, rs1, 1);
        rs1 += __shfl_xor_sync(0xffffffff, rs1, 2);
        l0 = l0 * corr0 + rs0;
        l1 = l1 * corr1 + rs1;
        #pragma unroll
        for (int nf = 0; nf < 8; nf++) {
            O[nf][0] *= corr0; O[nf][1] *= corr0;
            O[nf][2] *= corr1; O[nf][3] *= corr1;
        }
    };

    // one pipeline step: QK(t+1), PV(t), softmax(t+1)
    auto step = [&](int t, float (&Sc)[8][4], float (&Sn)[8][4]) {
        CP_WAIT(0);
        __syncthreads();
        if (t + 2 < NTILES) {
            size_t off = bhoff + (size_t)(t + 2) * 64 * HD;
            uint32_t bb = sbase + QREG + ((t + 2) % 3) * FBUF;
            cp_tile64(bb,           g_Khi + off, tid);
            cp_tile64(bb + FTS,     g_Klo + off, tid);
            cp_tile64(bb + 2 * FTS, g_Vhi + off, tid);
            cp_tile64(bb + 3 * FTS, g_Vlo + off, tid);
            CP_COMMIT();
        }
        qk_tile(t + 1, Sn);
        pv_tile(t, Sc);
        softmax_tile(Sn);
    };

    // ---- prologue: Q + tiles 0,1 ----
    cp_tile128(sbase,          g_Qhi + bhoff + (size_t)qrow0 * HD, tid);
    cp_tile128(sbase + FTS128, g_Qlo + bhoff + (size_t)qrow0 * HD, tid);
    {
        uint32_t bb = sbase + QREG;
        cp_tile64(bb,           g_Khi + bhoff, tid);
        cp_tile64(bb + FTS,     g_Klo + bhoff, tid);
        cp_tile64(bb + 2 * FTS, g_Vhi + bhoff, tid);
        cp_tile64(bb + 3 * FTS, g_Vlo + bhoff, tid);
        CP_COMMIT();
        size_t off = bhoff + (size_t)64 * HD;
        bb += FBUF;
        cp_tile64(bb,           g_Khi + off, tid);
        cp_tile64(bb + FTS,     g_Klo + off, tid);
        cp_tile64(bb + 2 * FTS, g_Vhi + off, tid);
        cp_tile64(bb + 3 * FTS, g_Vlo + off, tid);
        CP_COMMIT();
    }
    CP_WAIT(1);          // Q + tile0 landed
    __syncthreads();
    qk_tile(0, S0);
    softmax_tile(S0);    // P(0) packed in S0; O=0, m/l initialized

    // ---- main pipeline: t = 0..30 ----
    #pragma unroll 1
    for (int tp = 0; tp < 15; tp++) {
        step(2 * tp,     S0, S1);
        step(2 * tp + 1, S1, S0);
    }
    step(30, S0, S1);

    // ---- tail: PV(31) ----
    pv_tile(31, S1);

    // ---- epilogue: O/l -> bf16 hi/lo directly into g_Ahi/g_Alo ----
    float inv0 = 1.f / l0, inv1 = 1.f / l1;
    const int b = bh >> 4, h = bh & (NHEAD - 1);
    size_t base0 = ((size_t)(b * SEQ + r0)) * HID + h * HD;
    size_t base1 = base0 + (size_t)8 * HID;
    #pragma unroll
    for (int nf = 0; nf < 8; nf++) {
        int c = nf * 8 + cc;
        float v0 = O[nf][0] * inv0, v1 = O[nf][1] * inv0;
        float v2 = O[nf][2] * inv1, v3 = O[nf][3] * inv1;
        uint32_t h01 = packbf(v0, v1);
        uint32_t l01 = packbf(v0 - lo16f(h01), v1 - hi16f(h01));
        uint32_t h23 = packbf(v2, v3);
        uint32_t l23 = packbf(v2 - lo16f(h23), v3 - hi16f(h23));
        *(uint32_t*)(g_Ahi + base0 + c) = h01;
        *(uint32_t*)(g_Alo + base0 + c) = l01;
        *(uint32_t*)(g_Ahi + base1 + c) = h23;
        *(uint32_t*)(g_Alo + base1 + c) = l23;
    }
}

// ---------------------------------------------------------------------------
extern "C" void kernel_launch(void* const* d_in, const int* in_sizes, int n_in,
                              void* d_out, int out_size)
{
    (void)in_sizes; (void)n_in; (void)out_size;
    const float* x    = (const float*)d_in[0];
    const float* Wqkv = (const float*)d_in[2];
    const float* bqkv = (const float*)d_in[3];
    const float* Wout = (const float*)d_in[4];
    const float* bout = (const float*)d_in[5];
    float* out = (float*)d_out;

    float* p_qkv;
    __nv_bfloat16 *p_Xhi, *p_Xlo, *p_W1hi, *p_W1lo, *p_W2hi, *p_W2lo, *p_Ahi, *p_Alo;
    cudaGetSymbolAddress((void**)&p_qkv,  g_qkv);
    cudaGetSymbolAddress((void**)&p_Xhi,  g_Xhi);
    cudaGetSymbolAddress((void**)&p_Xlo,  g_Xlo);
    cudaGetSymbolAddress((void**)&p_W1hi, g_W1hi);
    cudaGetSymbolAddress((void**)&p_W1lo, g_W1lo);
    cudaGetSymbolAddress((void**)&p_W2hi, g_W2hi);
    cudaGetSymbolAddress((void**)&p_W2lo, g_W2lo);
    cudaGetSymbolAddress((void**)&p_Ahi,  g_Ahi);
    cudaGetSymbolAddress((void**)&p_Alo,  g_Alo);

    cudaFuncSetAttribute(gemm_mma_bf16x3,
                         cudaFuncAttributeMaxDynamicSharedMemorySize, GEMM_DSMEM);
    cudaFuncSetAttribute(flash_mma,
                         cudaFuncAttributeMaxDynamicSharedMemorySize, FDSMEM);

    // 1) split X into bf16 hi/lo
    split_f32<<<(MTOT * HID) / 256, 256>>>(x, p_Xhi, p_Xlo, MTOT * HID);
    // 2) transpose + split weights -> [N][K]
    transpose_split<<<dim3(QKVN / 32, HID / 32), dim3(32, 8)>>>(Wqkv, p_W1hi, p_W1lo, HID, QKVN);
    transpose_split<<<dim3(HID / 32, HID / 32), dim3(32, 8)>>>(Wout, p_W2hi, p_W2lo, HID, HID);
    // 3) QKV projection (warp MMA, bf16x3)
    gemm_mma_bf16x3<<<dim3(QKVN / 128, MTOT / 128), 256, GEMM_DSMEM>>>(
        p_Xhi, p_Xlo, p_W1hi, p_W1lo, bqkv, p_qkv, QKVN);
    // 4) RoPE + scatter -> bf16 hi/lo Q/K/V
    rope_scatter<<<(BATCH * NHEAD * SEQ * 32) / 256, 256>>>();
    // 5) flash attention, software-pipelined HMMA
    flash_mma<<<dim3(SEQ / 128, BATCH * NHEAD), 256, FDSMEM>>>();
    // 6) output projection (warp MMA, bf16x3)
    gemm_mma_bf16x3<<<dim3(HID / 128, MTOT / 128), 256, GEMM_DSMEM>>>(
        p_Ahi, p_Alo, p_W2hi, p_W2lo, bout, out, HID);
}

// round 17
// speedup vs baseline: 1.5295x; 1.5295x over previous
#include <cuda_runtime.h>
#include <cuda_bf16.h>
#include <math.h>
#include <stdint.h>

// Problem constants
#define BATCH 2
#define SEQ   2048
#define HID   1024
#define NHEAD 16
#define HD    64
#define QKVN  3072
#define MTOT  (BATCH * SEQ)   // 4096
#define GEMM_K 1024

// ---------------------------------------------------------------------------
// Scratch (device globals; no allocation allowed)
// ---------------------------------------------------------------------------
__device__ float g_qkv [MTOT * QKVN];

__device__ __nv_bfloat16 g_Xhi[MTOT * HID];
__device__ __nv_bfloat16 g_Xlo[MTOT * HID];
__device__ __nv_bfloat16 g_W1hi[QKVN * HID];
__device__ __nv_bfloat16 g_W1lo[QKVN * HID];
__device__ __nv_bfloat16 g_W2hi[HID * HID];
__device__ __nv_bfloat16 g_W2lo[HID * HID];
__device__ __nv_bfloat16 g_Ahi[MTOT * HID];
__device__ __nv_bfloat16 g_Alo[MTOT * HID];

#define BHSZ (BATCH * NHEAD * SEQ * HD)
__device__ __nv_bfloat16 g_Qhi[BHSZ];
__device__ __nv_bfloat16 g_Qlo[BHSZ];
__device__ __nv_bfloat16 g_Khi[BHSZ];
__device__ __nv_bfloat16 g_Klo[BHSZ];
__device__ __nv_bfloat16 g_Vhi[BHSZ];
__device__ __nv_bfloat16 g_Vlo[BHSZ];

// ---------------------------------------------------------------------------
// PTX helpers (compute_103-safe)
// ---------------------------------------------------------------------------
__device__ __forceinline__ uint32_t smem_u32(const void* p) {
    uint32_t a;
    asm("{ .reg .u64 t; cvta.to.shared.u64 t, %1; cvt.u32.u64 %0, t; }"
        : "=r"(a) : "l"(p));
    return a;
}

#define CP16(dst, src) \
    asm volatile("cp.async.ca.shared.global [%0], [%1], 16;" :: "r"(dst), "l"(src))
#define CP_COMMIT() asm volatile("cp.async.commit_group;" ::: "memory")
#define CP_WAIT(n)  asm volatile("cp.async.wait_group %0;" :: "n"(n) : "memory")

#define LDM4(r, a) \
    asm volatile("ldmatrix.sync.aligned.m8n8.x4.shared.b16 {%0,%1,%2,%3}, [%4];" \
        : "=r"((r)[0]), "=r"((r)[1]), "=r"((r)[2]), "=r"((r)[3]) : "r"(a))
#define LDM4T(r, a) \
    asm volatile("ldmatrix.sync.aligned.m8n8.x4.trans.shared.b16 {%0,%1,%2,%3}, [%4];" \
        : "=r"((r)[0]), "=r"((r)[1]), "=r"((r)[2]), "=r"((r)[3]) : "r"(a))
#define MMA_BF16(c, a, b) \
    asm volatile("mma.sync.aligned.m16n8k16.row.col.f32.bf16.bf16.f32 " \
        "{%0,%1,%2,%3}, {%4,%5,%6,%7}, {%8,%9}, {%0,%1,%2,%3};" \
        : "+f"((c)[0]), "+f"((c)[1]), "+f"((c)[2]), "+f"((c)[3]) \
        : "r"((a)[0]), "r"((a)[1]), "r"((a)[2]), "r"((a)[3]), \
          "r"((b)[0]), "r"((b)[1]))

__device__ __forceinline__ float ex2f(float x) {
    float y;
    asm("ex2.approx.f32 %0, %1;" : "=f"(y) : "f"(x));
    return y;
}
// pack two floats to bf16x2: lo half = a, hi half = b
__device__ __forceinline__ uint32_t packbf(float a, float b) {
    uint32_t d;
    asm("cvt.rn.bf16x2.f32 %0, %1, %2;" : "=r"(d) : "f"(b), "f"(a));
    return d;
}
__device__ __forceinline__ float lo16f(uint32_t h) { return __uint_as_float(h << 16); }
__device__ __forceinline__ float hi16f(uint32_t h) { return __uint_as_float(h & 0xffff0000u); }

__device__ __forceinline__ void wsplit(__nv_bfloat16* hi, __nv_bfloat16* lo,
                                       size_t i, float v) {
    __nv_bfloat16 h = __float2bfloat16(v);
    hi[i] = h;
    lo[i] = __float2bfloat16(v - __bfloat162float(h));
}

// ---------------------------------------------------------------------------
// Prep kernels
// ---------------------------------------------------------------------------
__global__ void split_f32(const float* __restrict__ in, __nv_bfloat16* __restrict__ hi,
                          __nv_bfloat16* __restrict__ lo, int n) {
    int i = blockIdx.x * 256 + threadIdx.x;
    if (i >= n) return;
    float v = in[i];
    __nv_bfloat16 h = __float2bfloat16(v);
    hi[i] = h;
    lo[i] = __float2bfloat16(v - __bfloat162float(h));
}

__global__ void transpose_split(const float* __restrict__ in, __nv_bfloat16* __restrict__ hi,
                                __nv_bfloat16* __restrict__ lo, int K, int N) {
    __shared__ float t[32][33];
    int n0 = blockIdx.x * 32, k0 = blockIdx.y * 32;
    int tx = threadIdx.x, ty = threadIdx.y;
    #pragma unroll
    for (int i = 0; i < 32; i += 8)
        t[ty + i][tx] = in[(size_t)(k0 + ty + i) * N + n0 + tx];
    __syncthreads();
    #pragma unroll
    for (int i = 0; i < 32; i += 8) {
        float v = t[tx][ty + i];
        size_t o = (size_t)(n0 + ty + i) * K + k0 + tx;
        __nv_bfloat16 h = __float2bfloat16(v);
        hi[o] = h;
        lo[o] = __float2bfloat16(v - __bfloat162float(h));
    }
}

// ---------------------------------------------------------------------------
// Warp-MMA bf16x3 GEMM. B-frags now loaded with LDM4 over nf-pairs
// (16 -> 12 ldmatrix instructions per warp-ks).
// ---------------------------------------------------------------------------
#define RS 40
#define TILE_SB  (128 * RS * 2)
#define BUF_SB   (4 * TILE_SB)
#define GEMM_DSMEM (2 * BUF_SB)

__device__ __forceinline__ void cp_tile(uint32_t dst, const __nv_bfloat16* __restrict__ src,
                                        int row0, int k0, int tid) {
    #pragma unroll
    for (int i = 0; i < 2; i++) {
        int idx = tid + i * 256;
        int r = idx >> 2, seg = idx & 3;
        CP16(dst + (uint32_t)(r * RS + seg * 8) * 2,
             src + (size_t)(row0 + r) * GEMM_K + k0 + seg * 8);
    }
}

__global__ __launch_bounds__(256) void gemm_mma_bf16x3(
    const __nv_bfloat16* __restrict__ Ahi, const __nv_bfloat16* __restrict__ Alo,
    const __nv_bfloat16* __restrict__ Bhi, const __nv_bfloat16* __restrict__ Blo,
    const float* __restrict__ bias, float* __restrict__ C, int N)
{
    extern __shared__ char dsm[];
    const uint32_t sbase = smem_u32(dsm);
    const int tid  = threadIdx.x;
    const int lane = tid & 31;
    const int wid  = tid >> 5;
    const int wm   = wid >> 2;
    const int wn   = wid & 3;
    const int m0 = blockIdx.y * 128;
    const int n0 = blockIdx.x * 128;

    float acc[4][4][4] = {};

    {
        uint32_t bb = sbase;
        cp_tile(bb,               Ahi, m0, 0, tid);
        cp_tile(bb + TILE_SB,     Alo, m0, 0, tid);
        cp_tile(bb + 2 * TILE_SB, Bhi, n0, 0, tid);
        cp_tile(bb + 3 * TILE_SB, Blo, n0, 0, tid);
        CP_COMMIT();
    }

    const int a_lr = lane & 15, a_lc = lane >> 4;
    // B-frag x4 lane addressing (same pattern as flash qk_tile)
    const uint32_t b_row = (lane & 7) + ((lane >> 4) & 1) * 8;
    const uint32_t b_col = ((lane >> 3) & 1) * 8;

    #pragma unroll 1
    for (int c = 0; c < GEMM_K / 32; c++) {
        if (c + 1 < GEMM_K / 32) {
            int k0 = (c + 1) * 32;
            uint32_t bb = sbase + ((c + 1) & 1) * BUF_SB;
            cp_tile(bb,               Ahi, m0, k0, tid);
            cp_tile(bb + TILE_SB,     Alo, m0, k0, tid);
            cp_tile(bb + 2 * TILE_SB, Bhi, n0, k0, tid);
            cp_tile(bb + 3 * TILE_SB, Blo, n0, k0, tid);
            CP_COMMIT();
            CP_WAIT(1);
        } else {
            CP_WAIT(0);
        }
        __syncthreads();

        uint32_t bb = sbase + (c & 1) * BUF_SB;
        #pragma unroll
        for (int ks = 0; ks < 2; ks++) {
            uint32_t Ah[4][4], Al[4][4], Bh[2][4], Bl[2][4];
            #pragma unroll
            for (int mf = 0; mf < 4; mf++) {
                uint32_t off = (uint32_t)((wm * 64 + mf * 16 + a_lr) * RS
                                          + ks * 16 + a_lc * 8) * 2;
                LDM4(Ah[mf], bb + off);
                LDM4(Al[mf], bb + TILE_SB + off);
            }
            #pragma unroll
            for (int pr = 0; pr < 2; pr++) {
                uint32_t off = (uint32_t)((wn * 32 + pr * 16 + b_row) * RS
                                          + ks * 16 + b_col) * 2;
                LDM4(Bh[pr], bb + 2 * TILE_SB + off);
                LDM4(Bl[pr], bb + 3 * TILE_SB + off);
            }
            #pragma unroll
            for (int mf = 0; mf < 4; mf++)
                #pragma unroll
                for (int nf = 0; nf < 4; nf++)
                    MMA_BF16(acc[mf][nf], Ah[mf], &Bh[nf >> 1][(nf & 1) * 2]);
            #pragma unroll
            for (int mf = 0; mf < 4; mf++)
                #pragma unroll
                for (int nf = 0; nf < 4; nf++)
                    MMA_BF16(acc[mf][nf], Ah[mf], &Bl[nf >> 1][(nf & 1) * 2]);
            #pragma unroll
            for (int mf = 0; mf < 4; mf++)
                #pragma unroll
                for (int nf = 0; nf < 4; nf++)
                    MMA_BF16(acc[mf][nf], Al[mf], &Bh[nf >> 1][(nf & 1) * 2]);
        }
        __syncthreads();
    }

    const int r0 = m0 + wm * 64 + (lane >> 2);
    const int c0 = n0 + wn * 32 + (lane & 3) * 2;
    #pragma unroll
    for (int mf = 0; mf < 4; mf++) {
        #pragma unroll
        for (int nf = 0; nf < 4; nf++) {
            int col = c0 + nf * 8;
            float bx = bias[col], by = bias[col + 1];
            int ra = r0 + mf * 16;
            float2 v0 = {acc[mf][nf][0] + bx, acc[mf][nf][1] + by};
            float2 v1 = {acc[mf][nf][2] + bx, acc[mf][nf][3] + by};
            *reinterpret_cast<float2*>(&C[(size_t)ra * N + col]) = v0;
            *reinterpret_cast<float2*>(&C[(size_t)(ra + 8) * N + col]) = v1;
        }
    }
}

// ---------------------------------------------------------------------------
// RoPE + scatter (R12 version)
// ---------------------------------------------------------------------------
#define QSCALE 0.1803368801111244f   // 0.125 * log2(e)

__global__ void rope_scatter()
{
    int i = blockIdx.x * blockDim.x + threadIdx.x;     // over (b,h,l,j), j<32
    const int total = BATCH * NHEAD * SEQ * 32;
    if (i >= total) return;

    int j = i & 31;
    int l = (i >> 5) & (SEQ - 1);
    int h = (i >> 16) & (NHEAD - 1);
    int b = i >> 20;

    const float* base = g_qkv + ((size_t)(b * SEQ + l)) * QKVN + h * 192;
    size_t o = ((((size_t)(b * NHEAD + h)) * SEQ + l) << 6) + j;   // [b][h][l][j]

    wsplit(g_Vhi, g_Vlo, o,      base[128 + j]);
    wsplit(g_Vhi, g_Vlo, o + 32, base[160 + j]);

    double e = -((double)(2 * j) / 64.0) * 13.287712379549449;  // log2(10000)
    float inv_freq = (float)exp2(e);
    float fr = (float)l * inv_freq;
    float c = cosf(fr), s = sinf(fr);

    float q1 = base[j],      q2 = base[j + 32];
    float k1 = base[64 + j], k2 = base[96 + j];

    wsplit(g_Qhi, g_Qlo, o,      (q1 * c - q2 * s) * QSCALE);
    wsplit(g_Qhi, g_Qlo, o + 32, (q1 * s + q2 * c) * QSCALE);
    wsplit(g_Khi, g_Klo, o,      k1 * c - k2 * s);
    wsplit(g_Khi, g_Klo, o + 32, k1 * s + k2 * c);
}

// ---------------------------------------------------------------------------
// Flash attention on HMMA (bf16x3 QK, split PV) — exact R12 version (737us):
// Q in smem, frags loaded per-np, S converted to Ph/Pl in place,
// 2-stage KV ring, 2 CTAs/SM.
// ---------------------------------------------------------------------------
#define FRS    72                        // smem row stride (bf16 elems) = 144B
#define FTS    (64 * FRS * 2)            // 9216 B per 64-row tile
#define FTS128 (128 * FRS * 2)           // 18432 B per 128-row tile
#define FBUF   (4 * FTS)                 // Khi,Klo,Vhi,Vlo = 36864 B
#define QREG   (2 * FTS128)              // Qhi,Qlo = 36864 B
#define FDSMEM (QREG + 2 * FBUF)         // 110592 B

__device__ __forceinline__ void cp_tile64(uint32_t dst, const __nv_bfloat16* __restrict__ src,
                                          int tid) {
    #pragma unroll
    for (int i = 0; i < 2; i++) {
        int idx = tid + i * 256;
        int r = idx >> 3, seg = idx & 7;
        CP16(dst + (uint32_t)(r * (FRS * 2) + seg * 16),
             src + (size_t)r * HD + seg * 8);
    }
}

__device__ __forceinline__ void cp_tile128(uint32_t dst, const __nv_bfloat16* __restrict__ src,
                                           int tid) {
    #pragma unroll
    for (int i = 0; i < 4; i++) {
        int idx = tid + i * 256;
        int r = idx >> 3, seg = idx & 7;
        CP16(dst + (uint32_t)(r * (FRS * 2) + seg * 16),
             src + (size_t)r * HD + seg * 8);
    }
}

__global__ __launch_bounds__(256, 2) void flash_mma()
{
    extern __shared__ char dsm[];
    const uint32_t sbase = smem_u32(dsm);
    const int tid  = threadIdx.x;
    const int lane = tid & 31;
    const int wid  = tid >> 5;
    const int bh   = blockIdx.y;

    const size_t bhoff = (size_t)bh * SEQ * HD;
    const int qrow0 = blockIdx.x * 128;
    const int r0 = qrow0 + wid * 16 + (lane >> 2);
    const int cc = (lane & 3) * 2;

    // stage Q (hi/lo) + KV tile 0 via cp.async
    cp_tile128(sbase,          g_Qhi + bhoff + (size_t)qrow0 * HD, tid);
    cp_tile128(sbase + FTS128, g_Qlo + bhoff + (size_t)qrow0 * HD, tid);
    {
        uint32_t bb = sbase + QREG;
        cp_tile64(bb,           g_Khi + bhoff, tid);
        cp_tile64(bb + FTS,     g_Klo + bhoff, tid);
        cp_tile64(bb + 2 * FTS, g_Vhi + bhoff, tid);
        cp_tile64(bb + 3 * FTS, g_Vlo + bhoff, tid);
        CP_COMMIT();
    }

    float O[8][4] = {};
    float m0 = -1e30f, m1 = -1e30f, l0 = 0.f, l1 = 0.f;

    // A-frag (Q) smem lane address
    const uint32_t qbase = sbase +
        (uint32_t)((wid * 16 + (lane & 15)) * FRS + (lane >> 4) * 8) * 2;
    // B-frag (K, non-trans) lane address components
    const uint32_t k_row = (lane & 7) + ((lane >> 4) & 1) * 8;
    const uint32_t k_col = ((lane >> 3) & 1) * 8;
    // B-frag (V, trans) lane address components
    const uint32_t v_row = (lane & 7) + ((lane >> 3) & 1) * 8;
    const uint32_t v_col = ((lane >> 4) & 1) * 8;

    #pragma unroll 1
    for (int t = 0; t < SEQ / 64; t++) {
        if (t + 1 < SEQ / 64) {
            size_t off = bhoff + (size_t)(t + 1) * 64 * HD;
            uint32_t bb = sbase + QREG + ((t + 1) & 1) * FBUF;
            cp_tile64(bb,           g_Khi + off, tid);
            cp_tile64(bb + FTS,     g_Klo + off, tid);
            cp_tile64(bb + 2 * FTS, g_Vhi + off, tid);
            cp_tile64(bb + 3 * FTS, g_Vlo + off, tid);
            CP_COMMIT();
            CP_WAIT(1);
        } else {
            CP_WAIT(0);
        }
        __syncthreads();

        const uint32_t kb = sbase + QREG + (t & 1) * FBUF;
        const uint32_t vb = kb + 2 * FTS;

        uint32_t Ph[4][4], Pl[4][4];

        {
            // ---- S = Q K^T (bf16x3) ----
            float S[8][4] = {};
            #pragma unroll
            for (int kc = 0; kc < 4; kc++) {
                uint32_t Qh[4], Ql[4];
                LDM4(Qh, qbase + kc * 32);
                LDM4(Ql, qbase + FTS128 + kc * 32);
                #pragma unroll
                for (int np = 0; np < 4; np++) {
                    uint32_t Bh[4], Bl[4];
                    uint32_t off = (np * 16 + k_row) * (FRS * 2) + (kc * 16 + k_col) * 2;
                    LDM4(Bh, kb + off);
                    LDM4(Bl, kb + FTS + off);
                    MMA_BF16(S[2 * np],     Qh, &Bh[0]);
                    MMA_BF16(S[2 * np + 1], Qh, &Bh[2]);
                    MMA_BF16(S[2 * np],     Qh, &Bl[0]);
                    MMA_BF16(S[2 * np + 1], Qh, &Bl[2]);
                    MMA_BF16(S[2 * np],     Ql, &Bh[0]);
                    MMA_BF16(S[2 * np + 1], Ql, &Bh[2]);
                }
            }

            // ---- online softmax ----
            float tm0 = -1e30f, tm1 = -1e30f;
            #pragma unroll
            for (int nf = 0; nf < 8; nf++) {
                tm0 = fmaxf(tm0, fmaxf(S[nf][0], S[nf][1]));
                tm1 = fmaxf(tm1, fmaxf(S[nf][2], S[nf][3]));
            }
            tm0 = fmaxf(tm0, __shfl_xor_sync(0xffffffff, tm0, 1));
            tm0 = fmaxf(tm0, __shfl_xor_sync(0xffffffff, tm0, 2));
            tm1 = fmaxf(tm1, __shfl_xor_sync(0xffffffff, tm1, 1));
            tm1 = fmaxf(tm1, __shfl_xor_sync(0xffffffff, tm1, 2));

            float mn0 = fmaxf(m0, tm0), mn1 = fmaxf(m1, tm1);
            float corr0 = ex2f(m0 - mn0), corr1 = ex2f(m1 - mn1);
            m0 = mn0; m1 = mn1;
            #pragma unroll
            for (int nf = 0; nf < 8; nf++) {
                O[nf][0] *= corr0; O[nf][1] *= corr0;
                O[nf][2] *= corr1; O[nf][3] *= corr1;
            }

            // ---- P = exp2(S - m), split hi/lo (in place of S) ----
            float rs0 = 0.f, rs1 = 0.f;
            #pragma unroll
            for (int nf = 0; nf < 8; nf++) {
                float p0 = ex2f(S[nf][0] - mn0), p1 = ex2f(S[nf][1] - mn0);
                float p2 = ex2f(S[nf][2] - mn1), p3 = ex2f(S[nf][3] - mn1);
                rs0 += p0 + p1;
                rs1 += p2 + p3;
                uint32_t h01 = packbf(p0, p1), h23 = packbf(p2, p3);
                uint32_t l01 = packbf(p0 - lo16f(h01), p1 - hi16f(h01));
                uint32_t l23 = packbf(p2 - lo16f(h23), p3 - hi16f(h23));
                int kc = nf >> 1, s = (nf & 1) * 2;
                Ph[kc][s] = h01; Ph[kc][s + 1] = h23;
                Pl[kc][s] = l01; Pl[kc][s + 1] = l23;
            }
            rs0 += __shfl_xor_sync(0xffffffff, rs0, 1);
            rs0 += __shfl_xor_sync(0xffffffff, rs0, 2);
            rs1 += __shfl_xor_sync(0xffffffff, rs1, 1);
            rs1 += __shfl_xor_sync(0xffffffff, rs1, 2);
            l0 = l0 * corr0 + rs0;
            l1 = l1 * corr1 + rs1;
        }

        // ---- O += P V (split), frags loaded per-np ----
        #pragma unroll
        for (int kc = 0; kc < 4; kc++) {
            #pragma unroll
            for (int np = 0; np < 4; np++) {
                uint32_t Vh[4], Vl[4];
                uint32_t off = (kc * 16 + v_row) * (FRS * 2) + (np * 16 + v_col) * 2;
                LDM4T(Vh, vb + off);
                LDM4T(Vl, vb + FTS + off);
                MMA_BF16(O[2 * np],     Ph[kc], &Vh[0]);
                MMA_BF16(O[2 * np + 1], Ph[kc], &Vh[2]);
                MMA_BF16(O[2 * np],     Ph[kc], &Vl[0]);
                MMA_BF16(O[2 * np + 1], Ph[kc], &Vl[2]);
                MMA_BF16(O[2 * np],     Pl[kc], &Vh[0]);
                MMA_BF16(O[2 * np + 1], Pl[kc], &Vh[2]);
            }
        }
        __syncthreads();
    }

    // ---- epilogue: O/l -> bf16 hi/lo directly into g_Ahi/g_Alo ----
    float inv0 = 1.f / l0, inv1 = 1.f / l1;
    const int b = bh >> 4, h = bh & (NHEAD - 1);
    size_t base0 = ((size_t)(b * SEQ + r0)) * HID + h * HD;
    size_t base1 = base0 + (size_t)8 * HID;
    #pragma unroll
    for (int nf = 0; nf < 8; nf++) {
        int c = nf * 8 + cc;
        float v0 = O[nf][0] * inv0, v1 = O[nf][1] * inv0;
        float v2 = O[nf][2] * inv1, v3 = O[nf][3] * inv1;
        uint32_t h01 = packbf(v0, v1);
        uint32_t l01 = packbf(v0 - lo16f(h01), v1 - hi16f(h01));
        uint32_t h23 = packbf(v2, v3);
        uint32_t l23 = packbf(v2 - lo16f(h23), v3 - hi16f(h23));
        *(uint32_t*)(g_Ahi + base0 + c) = h01;
        *(uint32_t*)(g_Alo + base0 + c) = l01;
        *(uint32_t*)(g_Ahi + base1 + c) = h23;
        *(uint32_t*)(g_Alo + base1 + c) = l23;
    }
}

// ---------------------------------------------------------------------------
extern "C" void kernel_launch(void* const* d_in, const int* in_sizes, int n_in,
                              void* d_out, int out_size)
{
    (void)in_sizes; (void)n_in; (void)out_size;
    const float* x    = (const float*)d_in[0];
    const float* Wqkv = (const float*)d_in[2];
    const float* bqkv = (const float*)d_in[3];
    const float* Wout = (const float*)d_in[4];
    const float* bout = (const float*)d_in[5];
    float* out = (float*)d_out;

    float* p_qkv;
    __nv_bfloat16 *p_Xhi, *p_Xlo, *p_W1hi, *p_W1lo, *p_W2hi, *p_W2lo, *p_Ahi, *p_Alo;
    cudaGetSymbolAddress((void**)&p_qkv,  g_qkv);
    cudaGetSymbolAddress((void**)&p_Xhi,  g_Xhi);
    cudaGetSymbolAddress((void**)&p_Xlo,  g_Xlo);
    cudaGetSymbolAddress((void**)&p_W1hi, g_W1hi);
    cudaGetSymbolAddress((void**)&p_W1lo, g_W1lo);
    cudaGetSymbolAddress((void**)&p_W2hi, g_W2hi);
    cudaGetSymbolAddress((void**)&p_W2lo, g_W2lo);
    cudaGetSymbolAddress((void**)&p_Ahi,  g_Ahi);
    cudaGetSymbolAddress((void**)&p_Alo,  g_Alo);

    cudaFuncSetAttribute(gemm_mma_bf16x3,
                         cudaFuncAttributeMaxDynamicSharedMemorySize, GEMM_DSMEM);
    cudaFuncSetAttribute(flash_mma,
                         cudaFuncAttributeMaxDynamicSharedMemorySize, FDSMEM);

    // 1) split X into bf16 hi/lo
    split_f32<<<(MTOT * HID) / 256, 256>>>(x, p_Xhi, p_Xlo, MTOT * HID);
    // 2) transpose + split weights -> [N][K]
    transpose_split<<<dim3(QKVN / 32, HID / 32), dim3(32, 8)>>>(Wqkv, p_W1hi, p_W1lo, HID, QKVN);
    transpose_split<<<dim3(HID / 32, HID / 32), dim3(32, 8)>>>(Wout, p_W2hi, p_W2lo, HID, HID);
    // 3) QKV projection (warp MMA, bf16x3)
    gemm_mma_bf16x3<<<dim3(QKVN / 128, MTOT / 128), 256, GEMM_DSMEM>>>(
        p_Xhi, p_Xlo, p_W1hi, p_W1lo, bqkv, p_qkv, QKVN);
    // 4) RoPE + scatter -> bf16 hi/lo Q/K/V
    rope_scatter<<<(BATCH * NHEAD * SEQ * 32) / 256, 256>>>();
    // 5) flash attention on tensor cores -> g_Ahi/g_Alo
    flash_mma<<<dim3(SEQ / 128, BATCH * NHEAD), 256, FDSMEM>>>();
    // 6) output projection (warp MMA, bf16x3)
    gemm_mma_bf16x3<<<dim3(HID / 128, MTOT / 128), 256, GEMM_DSMEM>>>(
        p_Ahi, p_Alo, p_W2hi, p_W2lo, bout, out, HID);
}